// round 2
// baseline (speedup 1.0000x reference)
#include <cuda_runtime.h>
#include <math.h>

#define NB 4096

// Per-box precomputed data: 4 float4 per box
//  v0 = (c0x,c0y,c1x,c1y)   corners 0,1
//  v1 = (c2x,c2y,c3x,c3y)   corners 2,3
//  v2 = (a0x,a0y,a1x,a1y)   axes 0,1 (unnormalized edge vectors)
//  v3 = (s0min,s0max,s1min,s1max) own-corner projections onto own axes
__device__ float4 g_boxdata[NB * 4];

__global__ void precompute_kernel(const float* __restrict__ boxes) {
    int i = blockIdx.x * blockDim.x + threadIdx.x;
    if (i >= NB) return;
    float cx  = boxes[i * 5 + 0];
    float cy  = boxes[i * 5 + 1];
    float w   = boxes[i * 5 + 2];
    float h   = boxes[i * 5 + 3];
    float ang = boxes[i * 5 + 4];
    float s, c;
    sincosf(ang, &s, &c);
    float hw = 0.5f * w, hh = 0.5f * h;

    // corner k: base=(ux*hw, uy*hh), unit=(-1,-1),(1,-1),(1,1),(-1,1)
    // x = bx*c + by*s + cx ; y = -bx*s + by*c + cy
    float c0x = -hw * c - hh * s + cx, c0y =  hw * s - hh * c + cy;
    float c1x =  hw * c - hh * s + cx, c1y = -hw * s - hh * c + cy;
    float c2x =  hw * c + hh * s + cx, c2y = -hw * s + hh * c + cy;
    float c3x = -hw * c + hh * s + cx, c3y =  hw * s + hh * c + cy;

    // axes
    float a0x = c1x - c0x, a0y = c1y - c0y;
    float a1x = c3x - c0x, a1y = c3y - c0y;

    // own projections onto axis 0
    float p0 = c0x * a0x + c0y * a0y;
    float p1 = c1x * a0x + c1y * a0y;
    float p2 = c2x * a0x + c2y * a0y;
    float p3 = c3x * a0x + c3y * a0y;
    float s0mn = fminf(fminf(p0, p1), fminf(p2, p3));
    float s0mx = fmaxf(fmaxf(p0, p1), fmaxf(p2, p3));
    // onto axis 1
    float q0 = c0x * a1x + c0y * a1y;
    float q1 = c1x * a1x + c1y * a1y;
    float q2 = c2x * a1x + c2y * a1y;
    float q3 = c3x * a1x + c3y * a1y;
    float s1mn = fminf(fminf(q0, q1), fminf(q2, q3));
    float s1mx = fmaxf(fmaxf(q0, q1), fmaxf(q2, q3));

    g_boxdata[i * 4 + 0] = make_float4(c0x, c0y, c1x, c1y);
    g_boxdata[i * 4 + 1] = make_float4(c2x, c2y, c3x, c3y);
    g_boxdata[i * 4 + 2] = make_float4(a0x, a0y, a1x, a1y);
    g_boxdata[i * 4 + 3] = make_float4(s0mn, s0mx, s1mn, s1mx);
}

// project 4 corners (v0,v1) onto axis (ax,ay); return min/max
__device__ __forceinline__ void proj_minmax(float ax, float ay,
                                            float4 v0, float4 v1,
                                            float& mn, float& mx) {
    float p0 = fmaf(v0.x, ax, v0.y * ay);
    float p1 = fmaf(v0.z, ax, v0.w * ay);
    float p2 = fmaf(v1.x, ax, v1.y * ay);
    float p3 = fmaf(v1.z, ax, v1.w * ay);
    mn = fminf(fminf(p0, p1), fminf(p2, p3));
    mx = fmaxf(fmaxf(p0, p1), fmaxf(p2, p3));
}

// returns giou1d + 1 = inter/union + union/hull  (len1 = mx1-mn1 precomputed)
__device__ __forceinline__ float giou_p1(float mn1, float mx1, float len1,
                                         float mn2, float mx2) {
    float inter = fmaxf(fminf(mx1, mx2) - fmaxf(mn1, mn2), 0.0f);
    float uni   = len1 + (mx2 - mn2) - inter;
    float hull  = fmaxf(mx1, mx2) - fminf(mn1, mn2);
    // (inter*hull + uni*uni) / (uni*hull)
    return __fdividef(fmaf(uni, uni, inter * hull), uni * hull);
}

// Tile: 32 rows (i) x 64 cols (j) per CTA. 256 threads; each does 4 i x 2 j.
__global__ __launch_bounds__(256) void pair_kernel(float* __restrict__ out) {
    __shared__ float4 sI[32 * 4];
    __shared__ float4 sJ[64 * 4];

    const int ti = blockIdx.y * 32;
    const int tj = blockIdx.x * 64;
    const int t  = threadIdx.x;

    if (t < 128) sI[t] = g_boxdata[ti * 4 + t];
    sJ[t] = g_boxdata[tj * 4 + t];
    __syncthreads();

    const int tx = t & 31;   // j lane
    const int ty = t >> 5;   // i group (0..7)

    // 2 j-boxes in registers
    float4 J0[2], J1[2], J2[2], J3[2];
    float je0[2], je1[2];
#pragma unroll
    for (int jj = 0; jj < 2; jj++) {
        int jl = tx + jj * 32;
        J0[jj] = sJ[jl * 4 + 0];
        J1[jj] = sJ[jl * 4 + 1];
        J2[jj] = sJ[jl * 4 + 2];
        J3[jj] = sJ[jl * 4 + 3];
        je0[jj] = J3[jj].y - J3[jj].x;
        je1[jj] = J3[jj].w - J3[jj].z;
    }

#pragma unroll
    for (int ii = 0; ii < 4; ii++) {
        int iloc = ty * 4 + ii;
        float4 I0 = sI[iloc * 4 + 0];
        float4 I1 = sI[iloc * 4 + 1];
        float4 I2 = sI[iloc * 4 + 2];
        float4 I3 = sI[iloc * 4 + 3];
        float ie0 = I3.y - I3.x;
        float ie1 = I3.w - I3.z;
        int gi = ti + iloc;

#pragma unroll
        for (int jj = 0; jj < 2; jj++) {
            float mn, mx;
            // i's axes vs j's corners (gA)
            proj_minmax(I2.x, I2.y, J0[jj], J1[jj], mn, mx);
            float g0 = giou_p1(I3.x, I3.y, ie0, mn, mx);
            proj_minmax(I2.z, I2.w, J0[jj], J1[jj], mn, mx);
            float g1 = giou_p1(I3.z, I3.w, ie1, mn, mx);
            // j's axes vs i's corners (gB) — giou1d is symmetric in its two intervals
            proj_minmax(J2[jj].x, J2[jj].y, I0, I1, mn, mx);
            float g2 = giou_p1(J3[jj].x, J3[jj].y, je0[jj], mn, mx);
            proj_minmax(J2[jj].z, J2[jj].w, I0, I1, mn, mx);
            float g3 = giou_p1(J3[jj].z, J3[jj].w, je1[jj], mn, mx);

            float gmin = fminf(fminf(g0, g1), fminf(g2, g3));
            // values above are g+1; final = clip(min(g), 0)
            float res = fmaxf(gmin - 1.0f, 0.0f);
            int gj = tj + tx + jj * 32;
            if (gi == gj) res = 0.0f;
            out[(size_t)gi * NB + gj] = res;
        }
    }
}

extern "C" void kernel_launch(void* const* d_in, const int* in_sizes, int n_in,
                              void* d_out, int out_size) {
    const float* boxes = (const float*)d_in[0];
    float* out = (float*)d_out;
    (void)in_sizes; (void)n_in; (void)out_size;

    precompute_kernel<<<NB / 256, 256>>>(boxes);
    pair_kernel<<<dim3(NB / 64, NB / 32), 256>>>(out);
}

// round 3
// speedup vs baseline: 1.6598x; 1.6598x over previous
#include <cuda_runtime.h>
#include <math.h>

#define NB 4096

// Per-box SAT data: 2 float4 per box
//  v0 = (cx, cy, a0x, a0y)    center + edge vector 0 (= corner1-corner0)
//  v1 = (a1x, a1y, L0, L1)    edge vector 1 (= corner3-corner0), L = |a|^2
__device__ float4 g_bd[NB * 2];

__global__ void precompute_kernel(const float* __restrict__ boxes) {
    int i = blockIdx.x * blockDim.x + threadIdx.x;
    if (i >= NB) return;
    float cx  = boxes[i * 5 + 0];
    float cy  = boxes[i * 5 + 1];
    float w   = boxes[i * 5 + 2];
    float h   = boxes[i * 5 + 3];
    float ang = boxes[i * 5 + 4];
    float s, c;
    sincosf(ang, &s, &c);
    // a0 = c1 - c0 = (w*c, -w*s);  a1 = c3 - c0 = (h*s, h*c)
    g_bd[i * 2 + 0] = make_float4(cx, cy, w * c, -w * s);
    g_bd[i * 2 + 1] = make_float4(h * s, h * c, w * w, h * h);
}

// giou1d + 1 in interval-length units.
// intervals: len La centered 0, len Lb centered d (symmetric in the two).
// inter = max(0, min(La, Lb, (La+Lb)/2 - |d|))
// hull  = max(La, Lb, (La+Lb)/2 + |d|)
// g+1   = inter/union + union/hull = (union^2 + inter*hull)/(union*hull)
__device__ __forceinline__ float giou_p1(float La, float Lb, float d) {
    float S    = La + Lb;
    float half = 0.5f * S;
    float ad   = fabsf(d);
    float t_in = half - ad;
    float t_h  = half + ad;
    float inter = fmaxf(fminf(fminf(La, Lb), t_in), 0.0f);
    float hull  = fmaxf(fmaxf(La, Lb), t_h);
    float uni   = S - inter;
    return __fdividef(fmaf(uni, uni, inter * hull), uni * hull);
}

// Tile: 32 rows (i) x 64 cols (j). 256 threads; each does 4 i x 2 j.
// Only tiles touching the upper triangle are computed (symmetry);
// results are mirrored to the lower triangle via an smem transpose.
__global__ __launch_bounds__(256) void pair_kernel(float* __restrict__ out) {
    const int rt = blockIdx.y;   // row tile (i / 32), 0..127
    const int ct = blockIdx.x;   // col tile (j / 64), 0..63
    if (rt > 2 * ct + 1) return; // tile entirely below diagonal -> covered by mirror

    __shared__ float4 sI[32 * 2];
    __shared__ float4 sJ[64 * 2];
    __shared__ float  smT[64][33];   // [jloc][iloc], padded

    const int ti = rt * 32;
    const int tj = ct * 64;
    const int t  = threadIdx.x;

    if (t < 64)  sI[t] = g_bd[ti * 2 + t];
    if (t < 128) sJ[t] = g_bd[tj * 2 + t];
    __syncthreads();

    const int tx = t & 31;   // j lane
    const int ty = t >> 5;   // i group (0..7)

    float4 Ja[2], Jb[2];
#pragma unroll
    for (int jj = 0; jj < 2; jj++) {
        int jl = tx + jj * 32;
        Ja[jj] = sJ[jl * 2 + 0];
        Jb[jj] = sJ[jl * 2 + 1];
    }

#pragma unroll
    for (int ii = 0; ii < 4; ii++) {
        const int iloc = ty * 4 + ii;
        const float4 Ia = sI[iloc * 2 + 0];
        const float4 Ib = sI[iloc * 2 + 1];
        const int gi = ti + iloc;

#pragma unroll
        for (int jj = 0; jj < 2; jj++) {
            const int jloc = tx + jj * 32;
            const float a0ix = Ia.z, a0iy = Ia.w, a1ix = Ib.x, a1iy = Ib.y;
            const float a0jx = Ja[jj].z, a0jy = Ja[jj].w;
            const float a1jx = Jb[jj].x, a1jy = Jb[jj].y;

            float dcx = Ja[jj].x - Ia.x;
            float dcy = Ja[jj].y - Ia.y;

            // cross dot products M[p][q] = a_p(i) . a_q(j), shared by both sides
            float M00 = fmaf(a0ix, a0jx, a0iy * a0jy);
            float M01 = fmaf(a0ix, a1jx, a0iy * a1jy);
            float M10 = fmaf(a1ix, a0jx, a1iy * a0jy);
            float M11 = fmaf(a1ix, a1jx, a1iy * a1jy);

            // center separation along each of the 4 axes
            float dA0 = fmaf(dcx, a0ix, dcy * a0iy);
            float dA1 = fmaf(dcx, a1ix, dcy * a1iy);
            float dB0 = fmaf(dcx, a0jx, dcy * a0jy);
            float dB1 = fmaf(dcx, a1jx, dcy * a1jy);

            // projected length of the other box on each axis
            float g0 = giou_p1(Ib.z,     fabsf(M00) + fabsf(M01), dA0);
            float g1 = giou_p1(Ib.w,     fabsf(M10) + fabsf(M11), dA1);
            float g2 = giou_p1(Jb[jj].z, fabsf(M00) + fabsf(M10), dB0);
            float g3 = giou_p1(Jb[jj].w, fabsf(M01) + fabsf(M11), dB1);

            float gmin = fminf(fminf(g0, g1), fminf(g2, g3));
            float res = fmaxf(gmin - 1.0f, 0.0f);
            int gj = tj + jloc;
            if (gi == gj) res = 0.0f;

            out[(size_t)gi * NB + gj] = res;
            smT[jloc][iloc] = res;
        }
    }

    __syncthreads();

    // mirror write: out[gj][gi], coalesced (4 threads per row, 8 floats each)
    const int r  = t >> 2;          // 0..63
    const int c0 = (t & 3) * 8;     // 0,8,16,24
    float v[8];
#pragma unroll
    for (int k = 0; k < 8; k++) v[k] = smT[r][c0 + k];
    size_t base = (size_t)(tj + r) * NB + ti + c0;
#pragma unroll
    for (int k = 0; k < 8; k++) out[base + k] = v[k];
}

extern "C" void kernel_launch(void* const* d_in, const int* in_sizes, int n_in,
                              void* d_out, int out_size) {
    const float* boxes = (const float*)d_in[0];
    float* out = (float*)d_out;
    (void)in_sizes; (void)n_in; (void)out_size;

    precompute_kernel<<<NB / 256, 256>>>(boxes);
    pair_kernel<<<dim3(NB / 64, NB / 32), 256>>>(out);
}

// round 7
// speedup vs baseline: 2.5556x; 1.5397x over previous
#include <cuda_runtime.h>
#include <math.h>

#define NB 4096

// giou1d + 1 in interval-length units.
// intervals: len La centered 0, len Lb centered d.
// g+1 = inter/union + union/hull = (union^2 + inter*hull)/(union*hull)
__device__ __forceinline__ float giou_p1(float La, float Lb, float d) {
    float S    = La + Lb;
    float half = 0.5f * S;
    float ad   = fabsf(d);
    float inter = fmaxf(fminf(fminf(La, Lb), half - ad), 0.0f);
    float hull  = fmaxf(fmaxf(La, Lb), half + ad);
    float uni   = S - inter;
    return __fdividef(fmaf(uni, uni, inter * hull), uni * hull);
}

// Per-box SAT data in smem: 2 float4 per box
//  v0 = (cx, cy, a0x, a0y)   center + edge vector 0
//  v1 = (a1x, a1y, L0, L1)   edge vector 1, L = |a|^2

template <bool DIAG>
__device__ __forceinline__ void compute_tile(
    const float4* __restrict__ sI, const float4* __restrict__ sJ,
    float (*smT)[33], float* __restrict__ out,
    int ti, int tj, int tx, int ty)
{
    float4 Ja[2], Jb[2];
#pragma unroll
    for (int jj = 0; jj < 2; jj++) {
        int jl = tx + jj * 32;
        Ja[jj] = sJ[jl * 2 + 0];
        Jb[jj] = sJ[jl * 2 + 1];
    }

#pragma unroll
    for (int ii = 0; ii < 4; ii++) {
        const int iloc = ty * 4 + ii;
        const float4 Ia = sI[iloc * 2 + 0];
        const float4 Ib = sI[iloc * 2 + 1];
        const int gi = ti + iloc;
        float* orow = out + (size_t)gi * NB + tj + tx;
        float* trow = &smT[tx][iloc];

#pragma unroll
        for (int jj = 0; jj < 2; jj++) {
            const float a0ix = Ia.z, a0iy = Ia.w, a1ix = Ib.x, a1iy = Ib.y;
            const float a0jx = Ja[jj].z, a0jy = Ja[jj].w;
            const float a1jx = Jb[jj].x, a1jy = Jb[jj].y;

            float dcx = Ja[jj].x - Ia.x;
            float dcy = Ja[jj].y - Ia.y;

            // cross dot products, shared by both boxes' axes
            float M00 = fmaf(a0ix, a0jx, a0iy * a0jy);
            float M01 = fmaf(a0ix, a1jx, a0iy * a1jy);
            float M10 = fmaf(a1ix, a0jx, a1iy * a0jy);
            float M11 = fmaf(a1ix, a1jx, a1iy * a1jy);

            // center separation along each of the 4 axes
            float dA0 = fmaf(dcx, a0ix, dcy * a0iy);
            float dA1 = fmaf(dcx, a1ix, dcy * a1iy);
            float dB0 = fmaf(dcx, a0jx, dcy * a0jy);
            float dB1 = fmaf(dcx, a1jx, dcy * a1jy);

            float g0 = giou_p1(Ib.z,     fabsf(M00) + fabsf(M01), dA0);
            float g1 = giou_p1(Ib.w,     fabsf(M10) + fabsf(M11), dA1);
            float g2 = giou_p1(Jb[jj].z, fabsf(M00) + fabsf(M10), dB0);
            float g3 = giou_p1(Jb[jj].w, fabsf(M01) + fabsf(M11), dB1);

            float gmin = fminf(fminf(g0, g1), fminf(g2, g3));
            float res = fmaxf(gmin - 1.0f, 0.0f);
            if (DIAG) {
                int gj = tj + tx + jj * 32;
                if (gi == gj) res = 0.0f;
            }

            orow[jj * 32] = res;
            trow[jj * 32 * 33] = res;
        }
    }
}

// One CTA per upper-triangle 32x64 tile. 256 threads; each does 4 i x 2 j.
// SAT data built in-smem from raw boxes (no precompute kernel).
__global__ __launch_bounds__(256) void pair_kernel(
    const float* __restrict__ boxes, float* __restrict__ out)
{
    __shared__ float4 sI[32 * 2];
    __shared__ float4 sJ[64 * 2];
    __shared__ float  smT[64][33];   // [jloc][iloc], padded

    // linear bid -> (ct, rt) over tiles with rt <= 2*ct+1
    // cumulative tiles before column ct: ct*(ct+1)
    const int b = blockIdx.x;
    int ct = (int)(0.5f * (sqrtf(4.0f * (float)b + 1.0f) - 1.0f));
    if ((ct + 1) * (ct + 2) <= b) ct++;
    if (ct * (ct + 1) > b) ct--;
    const int rt = b - ct * (ct + 1);

    const int ti = rt * 32;
    const int tj = ct * 64;
    const int t  = threadIdx.x;

    // Build SAT data for this tile's 96 boxes
    if (t < 96) {
        const int isJ = (t >= 32);
        const int loc = isJ ? (t - 32) : t;
        const int gb  = isJ ? (tj + loc) : (ti + loc);
        const float* bp = boxes + gb * 5;
        float cx = bp[0], cy = bp[1], w = bp[2], h = bp[3], ang = bp[4];
        float s, c;
        __sincosf(ang, &s, &c);
        float4 v0 = make_float4(cx, cy, w * c, -w * s);
        float4 v1 = make_float4(h * s, h * c, w * w, h * h);
        if (isJ) { sJ[loc * 2] = v0; sJ[loc * 2 + 1] = v1; }
        else     { sI[loc * 2] = v0; sI[loc * 2 + 1] = v1; }
    }
    __syncthreads();

    const int tx = t & 31;
    const int ty = t >> 5;

    if (rt >= 2 * ct) {  // straddle tile: contains diagonal
        compute_tile<true>(sI, sJ, smT, out, ti, tj, tx, ty);
    } else {
        compute_tile<false>(sI, sJ, smT, out, ti, tj, tx, ty);
    }

    __syncthreads();

    // mirror: out[tj+r][ti + lane], one full row per warp-STG (coalesced)
    const int w = ty;        // warp 0..7 -> rows 8w..8w+7
#pragma unroll
    for (int rr = 0; rr < 8; rr++) {
        int r = w * 8 + rr;
        out[(size_t)(tj + r) * NB + ti + tx] = smT[r][tx];
    }
}

extern "C" void kernel_launch(void* const* d_in, const int* in_sizes, int n_in,
                              void* d_out, int out_size) {
    const float* boxes = (const float*)d_in[0];
    float* out = (float*)d_out;
    (void)in_sizes; (void)n_in; (void)out_size;

    // number of tiles with rt <= 2*ct+1, ct in [0,64): sum(2ct+2) = 64*65 = 4160
    pair_kernel<<<4160, 256>>>(boxes, out);
}

// round 8
// speedup vs baseline: 2.7939x; 1.0933x over previous
#include <cuda_runtime.h>
#include <math.h>

#define NB 4096

// Per-box SAT data in smem: 2 float4 per box
//  v0 = (cx, cy, a0x, a0y)   center + edge vector 0 (corner1-corner0)
//  v1 = (a1x, a1y, L0, L1)   edge vector 1 (corner3-corner0), L = |a|^2

// giou1d slow path (only when no axis separates: t_in > 0 guaranteed).
// Returns g directly: g = N/D, N = uni^2 + hull*(inter-uni), D = uni*hull.
__device__ __forceinline__ float giou_slow(float La, float Lb, float S,
                                           float t_in, float d) {
    float th    = fmaf(0.5f, S, fabsf(d));
    float inter = fminf(fminf(La, Lb), t_in);   // > 0 here, no clamp needed
    float hull  = fmaxf(fmaxf(La, Lb), th);
    float uni   = S - inter;
    float tmp   = fmaf(2.0f, inter, -S);        // inter - uni
    float N     = fmaf(uni, uni, tmp * hull);
    float D     = uni * hull;
    return __fdividef(N, D);
}

template <bool DIAG>
__device__ __forceinline__ void compute_tile(
    const float4* __restrict__ sI, const float4* __restrict__ sJ,
    float (*smT)[33], float* __restrict__ out,
    int ti, int tj, int tx, int ty)
{
    float4 Ja[2], Jb[2];
#pragma unroll
    for (int jj = 0; jj < 2; jj++) {
        int jl = tx + jj * 32;
        Ja[jj] = sJ[jl * 2 + 0];
        Jb[jj] = sJ[jl * 2 + 1];
    }

#pragma unroll
    for (int ii = 0; ii < 4; ii++) {
        const int iloc = ty * 4 + ii;
        const float4 Ia = sI[iloc * 2 + 0];
        const float4 Ib = sI[iloc * 2 + 1];
        const int gi = ti + iloc;
        float* orow = out + (size_t)gi * NB + tj + tx;
        float* trow = &smT[tx][iloc];

#pragma unroll
        for (int jj = 0; jj < 2; jj++) {
            const float a0ix = Ia.z, a0iy = Ia.w, a1ix = Ib.x, a1iy = Ib.y;
            const float a0jx = Ja[jj].z, a0jy = Ja[jj].w;
            const float a1jx = Jb[jj].x, a1jy = Jb[jj].y;
            const float L0i = Ib.z, L1i = Ib.w;
            const float L0j = Jb[jj].z, L1j = Jb[jj].w;

            float dcx = Ja[jj].x - Ia.x;
            float dcy = Ja[jj].y - Ia.y;

            // cross dot products, shared by both boxes' axes
            float M00 = fmaf(a0ix, a0jx, a0iy * a0jy);
            float M01 = fmaf(a0ix, a1jx, a0iy * a1jy);
            float M10 = fmaf(a1ix, a0jx, a1iy * a0jy);
            float M11 = fmaf(a1ix, a1jx, a1iy * a1jy);

            // center separation along each of the 4 axes
            float dA0 = fmaf(dcx, a0ix, dcy * a0iy);
            float dA1 = fmaf(dcx, a1ix, dcy * a1iy);
            float dB0 = fmaf(dcx, a0jx, dcy * a0jy);
            float dB1 = fmaf(dcx, a1jx, dcy * a1jy);

            // other box's projected length on each axis
            float LbA0 = fabsf(M00) + fabsf(M01);
            float LbA1 = fabsf(M10) + fabsf(M11);
            float LbB0 = fabsf(M00) + fabsf(M10);
            float LbB1 = fabsf(M01) + fabsf(M11);

            float S0 = L0i + LbA0;
            float S1 = L1i + LbA1;
            float S2 = L0j + LbB0;
            float S3 = L1j + LbB1;

            // t_k = half_k - |d_k|; any t <= 0 -> separated on that axis -> res 0
            float t0 = fmaf(0.5f, S0, -fabsf(dA0));
            float t1 = fmaf(0.5f, S1, -fabsf(dA1));
            float t2 = fmaf(0.5f, S2, -fabsf(dB0));
            float t3 = fmaf(0.5f, S3, -fabsf(dB1));
            float m = fminf(fminf(t0, t1), fminf(t2, t3));

            float res = 0.0f;
            if (m > 0.0f) {
                float g0 = giou_slow(L0i, LbA0, S0, t0, dA0);
                float g1 = giou_slow(L1i, LbA1, S1, t1, dA1);
                float g2 = giou_slow(L0j, LbB0, S2, t2, dB0);
                float g3 = giou_slow(L1j, LbB1, S3, t3, dB1);
                res = fmaxf(fminf(fminf(g0, g1), fminf(g2, g3)), 0.0f);
            }

            if (DIAG) {
                int gj = tj + tx + jj * 32;
                if (gi == gj) res = 0.0f;
            }

            orow[jj * 32] = res;
            trow[jj * 32 * 33] = res;
        }
    }
}

// One CTA per upper-triangle 32x64 tile. 256 threads; each does 4 i x 2 j.
__global__ __launch_bounds__(256) void pair_kernel(
    const float* __restrict__ boxes, float* __restrict__ out)
{
    __shared__ float4 sI[32 * 2];
    __shared__ float4 sJ[64 * 2];
    __shared__ float  smT[64][33];   // [jloc][iloc], padded

    // linear bid -> (ct, rt) over tiles with rt <= 2*ct+1
    const int b = blockIdx.x;
    int ct = (int)(0.5f * (sqrtf(4.0f * (float)b + 1.0f) - 1.0f));
    if ((ct + 1) * (ct + 2) <= b) ct++;
    if (ct * (ct + 1) > b) ct--;
    const int rt = b - ct * (ct + 1);

    const int ti = rt * 32;
    const int tj = ct * 64;
    const int t  = threadIdx.x;

    // Build SAT data for this tile's 96 boxes
    if (t < 96) {
        const int isJ = (t >= 32);
        const int loc = isJ ? (t - 32) : t;
        const int gb  = isJ ? (tj + loc) : (ti + loc);
        const float* bp = boxes + gb * 5;
        float cx = bp[0], cy = bp[1], w = bp[2], h = bp[3], ang = bp[4];
        float s, c;
        __sincosf(ang, &s, &c);
        float4 v0 = make_float4(cx, cy, w * c, -w * s);
        float4 v1 = make_float4(h * s, h * c, w * w, h * h);
        if (isJ) { sJ[loc * 2] = v0; sJ[loc * 2 + 1] = v1; }
        else     { sI[loc * 2] = v0; sI[loc * 2 + 1] = v1; }
    }
    __syncthreads();

    const int tx = t & 31;
    const int ty = t >> 5;

    if (rt >= 2 * ct) {  // straddle tile: contains diagonal
        compute_tile<true>(sI, sJ, smT, out, ti, tj, tx, ty);
    } else {
        compute_tile<false>(sI, sJ, smT, out, ti, tj, tx, ty);
    }

    __syncthreads();

    // mirror: out[tj+r][ti + lane], one full row per warp-STG (coalesced)
#pragma unroll
    for (int rr = 0; rr < 8; rr++) {
        int r = ty * 8 + rr;
        out[(size_t)(tj + r) * NB + ti + tx] = smT[r][tx];
    }
}

extern "C" void kernel_launch(void* const* d_in, const int* in_sizes, int n_in,
                              void* d_out, int out_size) {
    const float* boxes = (const float*)d_in[0];
    float* out = (float*)d_out;
    (void)in_sizes; (void)n_in; (void)out_size;

    pair_kernel<<<4160, 256>>>(boxes, out);
}